// round 7
// baseline (speedup 1.0000x reference)
#include <cuda_runtime.h>
#include <cuda_bf16.h>
#include <math.h>
#include <stdint.h>

#define NT 9
#define NN 50000
#define NE 800000
#define NREL 15
#define DIN 64
#define HH 128
#define GBLK ((NN + 127) / 128)        // 391 gemm blocks per type

__device__ __constant__ int   c_src[NREL]   = {0,1,0,2,1,0,3,3,0,4,0,1,0,0,5};
__device__ __constant__ int   c_dst[NREL]   = {1,0,2,0,2,3,0,7,4,0,8,4,6,5,0};
__device__ __constant__ float c_invcnt[NT]  = {1.f/5.f,1.f,1.f/2.f,1.f,1.f/2.f,1.f,1.f,1.f,1.f};
__device__ __constant__ int   c_nseg[NT]    = {6,2,3,2,3,2,2,2,2};
__device__ __constant__ int   c_segrel[NT][6] = {
    {-1,1,3,6,9,14},{-1,0,0,0,0,0},{-1,2,4,0,0,0},{-1,5,0,0,0,0},
    {-1,8,11,0,0,0},{-1,13,0,0,0,0},{-1,12,0,0,0,0},{-1,7,0,0,0,0},{-1,10,0,0,0,0}};

// Scratch (device globals: allocation-free rule)
__device__ float g_xs0[(size_t)NT*NN*HH];
__device__ float g_xs1[(size_t)NT*NN*HH];
__device__ __nv_bfloat16 g_xbfA[(size_t)NT*NN*HH];
__device__ __nv_bfloat16 g_xbfB[(size_t)NT*NN*HH];
__device__ float g_msgs[(size_t)NREL*NN*HH];   // uniform 128-stride, all layers
__device__ int   g_cnt[NREL*NN];
__device__ int   g_off[NREL*(NN+1)];
__device__ int   g_tmp[NREL*NN];
__device__ int   g_csrc[(size_t)NREL*NE];
__device__ float g_wrc[3ull*NT*HH*HH];
__device__ float g_bc[3*NT*HH];
__device__ int   g_done[3][NT];                // gemm completion counters

// ---------------------------------------------------------------------------
// zero counters + convert input x to bf16 shadow A
// ---------------------------------------------------------------------------
__global__ void k_cvt_zero(const float* __restrict__ x) {
    int i = blockIdx.x * blockDim.x + threadIdx.x;
    if (i < NREL * NN) g_cnt[i] = 0;
    if (i < 3 * NT) ((int*)g_done)[i] = 0;
    if (i < NT * NN * DIN / 2) {
        float2 v = reinterpret_cast<const float2*>(x)[i];
        reinterpret_cast<__nv_bfloat162*>(g_xbfA)[i] = __floats2bfloat162_rn(v.x, v.y);
    }
}

__global__ void k_hist(const int* __restrict__ edges) {
    int i = blockIdx.x * blockDim.x + threadIdx.x;
    if (i >= NREL * NE) return;
    int r = i / NE;
    int e = i - r * NE;
    int dst = edges[(size_t)r * 2 * NE + NE + e];
    atomicAdd(&g_cnt[r * NN + dst], 1);
}

__global__ void k_scan() {
    int r = blockIdx.x;
    int t = threadIdx.x;
    __shared__ int s[1024];
    int carry = 0;
    for (int base = 0; base < NN; base += 1024) {
        int i = base + t;
        int v = (i < NN) ? g_cnt[r * NN + i] : 0;
        s[t] = v;
        __syncthreads();
        #pragma unroll
        for (int d = 1; d < 1024; d <<= 1) {
            int x = (t >= d) ? s[t - d] : 0;
            __syncthreads();
            s[t] += x;
            __syncthreads();
        }
        int excl = carry + s[t] - v;
        if (i < NN) {
            g_off[r * (NN + 1) + i] = excl;
            g_tmp[r * NN + i] = excl;
        }
        carry += s[1023];
        __syncthreads();
    }
    if (t == 0) g_off[r * (NN + 1) + NN] = carry;
}

__global__ void k_fill(const int* __restrict__ edges) {
    int i = blockIdx.x * blockDim.x + threadIdx.x;
    if (i >= NREL * NE) return;
    int r = i / NE;
    int e = i - r * NE;
    int src = edges[(size_t)r * 2 * NE + e];
    int dst = edges[(size_t)r * 2 * NE + NE + e];
    int pos = atomicAdd(&g_tmp[r * NN + dst], 1);
    g_csrc[(size_t)r * NE + pos] = src;
}

// ---------------------------------------------------------------------------
// Combine Wr / b across relations sharing a dst type
// ---------------------------------------------------------------------------
template <int K>
__global__ void k_combW(const float* __restrict__ Wr, float* __restrict__ wrc) {
    int idx = blockIdx.x * blockDim.x + threadIdx.x;
    if (idx >= NT * K * HH) return;
    int i = idx / (K * HH);
    int j = idx - i * (K * HH);
    float s = 0.f;
    #pragma unroll
    for (int r = 0; r < NREL; r++)
        if (c_dst[r] == i) s += Wr[(size_t)r * K * HH + j];
    wrc[(size_t)i * K * HH + j] = s;
}

__global__ void k_combB(const float* __restrict__ b, float* __restrict__ bc) {
    int idx = blockIdx.x * blockDim.x + threadIdx.x;
    if (idx >= NT * HH) return;
    int i = idx / HH;
    int j = idx - i * HH;
    float s = 0.f;
    #pragma unroll
    for (int r = 0; r < NREL; r++)
        if (c_dst[r] == i) s += b[r * HH + j];
    bc[i * HH + j] = s;
}

// ---------------------------------------------------------------------------
// Layer-1 aggregation (standalone): D=64, warp per row, 8 rows/block.
// Output at 128-float row stride (uniform msgs layout).
// ---------------------------------------------------------------------------
__global__ void k_agg1() {
    int r = blockIdx.y;
    int row = blockIdx.x * 8 + threadIdx.y;
    int t = threadIdx.x;
    const __nv_bfloat16* __restrict__ xsrc = g_xbfA + (size_t)c_src[r] * NN * DIN;
    int o0 = g_off[r * (NN + 1) + row];
    int o1 = g_off[r * (NN + 1) + row + 1];
    const int* __restrict__ srcs = g_csrc + (size_t)r * NE;
    float ax = 0.f, ay = 0.f, bxx = 0.f, byy = 0.f;
    int e = o0;
    for (; e + 2 <= o1; e += 2) {
        int s0 = srcs[e], s1 = srcs[e + 1];
        float2 p = __bfloat1622float2(*reinterpret_cast<const __nv_bfloat162*>(xsrc + (size_t)s0 * DIN + t * 2));
        float2 q = __bfloat1622float2(*reinterpret_cast<const __nv_bfloat162*>(xsrc + (size_t)s1 * DIN + t * 2));
        ax += p.x; ay += p.y; bxx += q.x; byy += q.y;
    }
    if (e < o1) {
        float2 p = __bfloat1622float2(*reinterpret_cast<const __nv_bfloat162*>(xsrc + (size_t)srcs[e] * DIN + t * 2));
        ax += p.x; ay += p.y;
    }
    float inv = (o1 > o0) ? 1.f / (float)(o1 - o0) : 0.f;
    float2 o = make_float2((ax + bxx) * inv, (ay + byy) * inv);
    *reinterpret_cast<float2*>(g_msgs + (size_t)r * NN * HH + (size_t)row * HH + t * 2) = o;
}

// ---------------------------------------------------------------------------
// TF32 mma helpers
// ---------------------------------------------------------------------------
__device__ __forceinline__ uint32_t f2tf32(float f) {
    uint32_t u;
    asm("cvt.rna.tf32.f32 %0, %1;" : "=r"(u) : "f"(f));
    return u;
}

__device__ __forceinline__ void mma_tf32(float* d, const uint32_t* a, const uint32_t* b) {
    asm volatile(
        "mma.sync.aligned.m16n8k8.row.col.f32.tf32.tf32.f32 "
        "{%0,%1,%2,%3}, {%4,%5,%6,%7}, {%8,%9}, {%0,%1,%2,%3};"
        : "+f"(d[0]), "+f"(d[1]), "+f"(d[2]), "+f"(d[3])
        : "r"(a[0]), "r"(a[1]), "r"(a[2]), "r"(a[3]), "r"(b[0]), "r"(b[1]));
}

#define APAD 36
#define BPAD 136

// ---------------------------------------------------------------------------
// Mega kernel: [GEMM+LN blocks for layer L (9 types x GBLK)] then either
//  - next-layer aggregation blocks (spin on g_done[L]) [HASAGG], or
//  - final FC+sigmoid blocks (spin on all 9 counters)  [HASFINAL].
// ---------------------------------------------------------------------------
template <int SEGK, bool WRITEBF, bool HASAGG, bool HASFINAL>
__global__ void __launch_bounds__(256) k_mega(
    int L,
    const float* __restrict__ xin, const float* __restrict__ Wl,
    const float* __restrict__ wrc, const float* __restrict__ bc,
    const float* __restrict__ gam, const float* __restrict__ bet,
    float* __restrict__ out, __nv_bfloat16* __restrict__ xbf_out,
    const float* __restrict__ Wfc, const float* __restrict__ bfc,
    float* __restrict__ finout)
{
    __shared__ uint32_t sA[128 * APAD];
    __shared__ uint32_t sB[32 * BPAD];

    int bid = blockIdx.x;
    int tid = threadIdx.x;
    int lane = tid & 31;

    if (bid < NT * GBLK) {
        // ================= GEMM + LN =================
        int type = bid / GBLK;
        int r0 = (bid - type * GBLK) * 128;
        int w = tid >> 5;

        float acc[16][4];
        #pragma unroll
        for (int nt = 0; nt < 16; nt++)
            #pragma unroll
            for (int j = 0; j < 4; j++) acc[nt][j] = 0.f;

        int nseg = c_nseg[type];
        for (int seg = 0; seg < nseg; seg++) {
            int rel = c_segrel[type][seg];
            const float* Abase; int lda;
            const float* Bbase;
            if (seg == 0) {
                Abase = xin + (size_t)type * NN * SEGK; lda = SEGK;
                Bbase = wrc + (size_t)type * SEGK * HH;
            } else {
                Abase = g_msgs + (size_t)rel * NN * HH; lda = HH;
                Bbase = Wl + (size_t)rel * SEGK * HH;
            }
            #pragma unroll
            for (int off = 0; off < SEGK; off += 32) {
                __syncthreads();
                #pragma unroll
                for (int l = 0; l < 4; l++) {
                    int f = tid + l * 256;
                    int row = f >> 3;
                    int c0 = (f & 7) * 4;
                    float4 v = make_float4(0.f, 0.f, 0.f, 0.f);
                    if (r0 + row < NN)
                        v = *reinterpret_cast<const float4*>(
                            Abase + (size_t)(r0 + row) * lda + off + c0);
                    uint4 u;
                    u.x = f2tf32(v.x); u.y = f2tf32(v.y);
                    u.z = f2tf32(v.z); u.w = f2tf32(v.w);
                    *reinterpret_cast<uint4*>(&sA[row * APAD + c0]) = u;
                }
                #pragma unroll
                for (int l = 0; l < 4; l++) {
                    int f = tid + l * 256;
                    int krow = f >> 5;
                    int n0 = (f & 31) * 4;
                    float4 v = *reinterpret_cast<const float4*>(
                        Bbase + (size_t)(off + krow) * HH + n0);
                    uint4 u;
                    u.x = f2tf32(v.x); u.y = f2tf32(v.y);
                    u.z = f2tf32(v.z); u.w = f2tf32(v.w);
                    *reinterpret_cast<uint4*>(&sB[krow * BPAD + n0]) = u;
                }
                __syncthreads();
                #pragma unroll
                for (int kt = 0; kt < 4; kt++) {
                    int abase = (w * 16 + (lane >> 2)) * APAD + kt * 8 + (lane & 3);
                    uint32_t af[4];
                    af[0] = sA[abase];
                    af[1] = sA[abase + 8 * APAD];
                    af[2] = sA[abase + 4];
                    af[3] = sA[abase + 8 * APAD + 4];
                    int bb = (kt * 8 + (lane & 3)) * BPAD + (lane >> 2);
                    #pragma unroll
                    for (int nt = 0; nt < 16; nt++) {
                        uint32_t bf[2];
                        bf[0] = sB[bb + nt * 8];
                        bf[1] = sB[bb + nt * 8 + 4 * BPAD];
                        mma_tf32(acc[nt], af, bf);
                    }
                }
            }
        }

        float inv = c_invcnt[type];
        #pragma unroll
        for (int h = 0; h < 2; h++) {
            int row = r0 + w * 16 + (lane >> 2) + h * 8;
            float v[16][2];
            float s = 0.f;
            #pragma unroll
            for (int nt = 0; nt < 16; nt++) {
                int col = nt * 8 + (lane & 3) * 2;
                float x0 = (acc[nt][2 * h] + bc[type * HH + col]) * inv;
                float x1 = (acc[nt][2 * h + 1] + bc[type * HH + col + 1]) * inv;
                x0 = (x0 >= 0.f) ? x0 : 0.01f * x0;
                x1 = (x1 >= 0.f) ? x1 : 0.01f * x1;
                v[nt][0] = x0; v[nt][1] = x1;
                s += x0 + x1;
            }
            s += __shfl_xor_sync(0xffffffffu, s, 1);
            s += __shfl_xor_sync(0xffffffffu, s, 2);
            float mu = s * (1.f / HH);
            float q = 0.f;
            #pragma unroll
            for (int nt = 0; nt < 16; nt++) {
                float d0 = v[nt][0] - mu, d1 = v[nt][1] - mu;
                v[nt][0] = d0; v[nt][1] = d1;
                q += d0 * d0 + d1 * d1;
            }
            q += __shfl_xor_sync(0xffffffffu, q, 1);
            q += __shfl_xor_sync(0xffffffffu, q, 2);
            float rs = rsqrtf(q * (1.f / HH) + 1e-5f);
            if (row < NN) {
                float* op = out + (size_t)type * NN * HH + (size_t)row * HH;
                #pragma unroll
                for (int nt = 0; nt < 16; nt++) {
                    int col = nt * 8 + (lane & 3) * 2;
                    float2 o;
                    o.x = v[nt][0] * rs * gam[col] + bet[col];
                    o.y = v[nt][1] * rs * gam[col + 1] + bet[col + 1];
                    *reinterpret_cast<float2*>(op + col) = o;
                    if (WRITEBF) {
                        __nv_bfloat16* obf = xbf_out + (size_t)type * NN * HH + (size_t)row * HH;
                        *reinterpret_cast<__nv_bfloat162*>(obf + col) =
                            __floats2bfloat162_rn(o.x, o.y);
                    }
                }
            }
        }
        // signal completion of this type's tile
        __threadfence();
        __syncthreads();
        if (tid == 0) atomicAdd(&g_done[L][type], 1);
        return;
    }

    int xid = bid - NT * GBLK;

    if (HASAGG) {
        // ============ next-layer aggregation (D=128), 8 rows/block ============
        int r = xid % NREL;
        int rowblk = xid / NREL;
        if (tid == 0) {
            int s = c_src[r], d = c_dst[r];
            while (*(volatile int*)&g_done[L][s] < GBLK ||
                   *(volatile int*)&g_done[L][d] < GBLK)
                __nanosleep(200);
        }
        __syncthreads();

        int ty = tid >> 5;
        int t = lane;
        int row = rowblk * 8 + ty;
        const __nv_bfloat16* __restrict__ xsrc = xbf_out + (size_t)c_src[r] * NN * HH;
        int o0 = g_off[r * (NN + 1) + row];
        int o1 = g_off[r * (NN + 1) + row + 1];
        const int* __restrict__ srcs = g_csrc + (size_t)r * NE;
        float ax[4] = {0.f, 0.f, 0.f, 0.f};
        float bx[4] = {0.f, 0.f, 0.f, 0.f};
        int e = o0;
        for (; e + 2 <= o1; e += 2) {
            int s0 = srcs[e], s1 = srcs[e + 1];
            uint2 u0 = *reinterpret_cast<const uint2*>(xsrc + (size_t)s0 * HH + t * 4);
            uint2 u1 = *reinterpret_cast<const uint2*>(xsrc + (size_t)s1 * HH + t * 4);
            float2 p0 = __bfloat1622float2(*reinterpret_cast<__nv_bfloat162*>(&u0.x));
            float2 p1 = __bfloat1622float2(*reinterpret_cast<__nv_bfloat162*>(&u0.y));
            float2 q0 = __bfloat1622float2(*reinterpret_cast<__nv_bfloat162*>(&u1.x));
            float2 q1 = __bfloat1622float2(*reinterpret_cast<__nv_bfloat162*>(&u1.y));
            ax[0] += p0.x; ax[1] += p0.y; ax[2] += p1.x; ax[3] += p1.y;
            bx[0] += q0.x; bx[1] += q0.y; bx[2] += q1.x; bx[3] += q1.y;
        }
        if (e < o1) {
            uint2 u0 = *reinterpret_cast<const uint2*>(xsrc + (size_t)srcs[e] * HH + t * 4);
            float2 p0 = __bfloat1622float2(*reinterpret_cast<__nv_bfloat162*>(&u0.x));
            float2 p1 = __bfloat1622float2(*reinterpret_cast<__nv_bfloat162*>(&u0.y));
            ax[0] += p0.x; ax[1] += p0.y; ax[2] += p1.x; ax[3] += p1.y;
        }
        float inv = (o1 > o0) ? 1.f / (float)(o1 - o0) : 0.f;
        float4 o;
        o.x = (ax[0] + bx[0]) * inv; o.y = (ax[1] + bx[1]) * inv;
        o.z = (ax[2] + bx[2]) * inv; o.w = (ax[3] + bx[3]) * inv;
        *reinterpret_cast<float4*>(g_msgs + (size_t)r * NN * HH + (size_t)row * HH + t * 4) = o;
        return;
    }

    if (HASFINAL) {
        // ============ final FC + sigmoid: 2 nodes/block ============
        if (tid == 0) {
            bool ok = false;
            while (!ok) {
                ok = true;
                #pragma unroll
                for (int i = 0; i < NT; i++)
                    if (*(volatile int*)&g_done[L][i] < GBLK) { ok = false; break; }
                if (!ok) __nanosleep(200);
            }
        }
        __syncthreads();

        __shared__ float sh[8];
        int half = tid >> 7;
        int t = tid & 127;
        int n = xid * 2 + half;
        float p = 0.f;
        #pragma unroll
        for (int i = 0; i < NT; i++)
            p += out[((size_t)i * NN + n) * HH + t] * Wfc[i * HH + t];
        #pragma unroll
        for (int o = 16; o > 0; o >>= 1) p += __shfl_xor_sync(0xffffffffu, p, o);
        int w = tid >> 5;
        if ((tid & 31) == 0) sh[w] = p;
        __syncthreads();
        if (t == 0) {
            float tot = sh[half * 4] + sh[half * 4 + 1] + sh[half * 4 + 2] + sh[half * 4 + 3];
            finout[n] = 1.f / (1.f + expf(-(tot + bfc[0])));
        }
    }
}

// ---------------------------------------------------------------------------
// Host driver: single stream, three mega launches
// ---------------------------------------------------------------------------
extern "C" void kernel_launch(void* const* d_in, const int* in_sizes, int n_in,
                              void* d_out, int out_size) {
    const float* x    = (const float*)d_in[0];
    const int* edges  = (const int*)d_in[1];
    const float* Wl[3]  = {(const float*)d_in[2], (const float*)d_in[5], (const float*)d_in[8]};
    const float* Wr[3]  = {(const float*)d_in[3], (const float*)d_in[6], (const float*)d_in[9]};
    const float* bb[3]  = {(const float*)d_in[4], (const float*)d_in[7], (const float*)d_in[10]};
    const float* gam[3] = {(const float*)d_in[11], (const float*)d_in[13], (const float*)d_in[15]};
    const float* bet[3] = {(const float*)d_in[12], (const float*)d_in[14], (const float*)d_in[16]};
    const float* Wfc  = (const float*)d_in[17];
    const float* bfc  = (const float*)d_in[18];
    float* out = (float*)d_out;

    float *p_xs0, *p_xs1, *p_wrc, *p_bc;
    __nv_bfloat16 *p_xbfA, *p_xbfB;
    cudaGetSymbolAddress((void**)&p_xs0, g_xs0);
    cudaGetSymbolAddress((void**)&p_xs1, g_xs1);
    cudaGetSymbolAddress((void**)&p_wrc, g_wrc);
    cudaGetSymbolAddress((void**)&p_bc, g_bc);
    cudaGetSymbolAddress((void**)&p_xbfA, g_xbfA);
    cudaGetSymbolAddress((void**)&p_xbfB, g_xbfB);

    size_t wstride = (size_t)NT * HH * HH;

    // CSR build + weight prep (single stream)
    k_cvt_zero<<<(NT * NN * DIN / 2 + 255) / 256, 256>>>(x);
    k_hist<<<(NREL * NE + 255) / 256, 256>>>(edges);
    k_scan<<<NREL, 1024>>>();
    k_fill<<<(NREL * NE + 255) / 256, 256>>>(edges);
    k_combW<DIN><<<(NT * DIN * HH + 255) / 256, 256>>>(Wr[0], p_wrc);
    k_combW<HH><<<(NT * HH * HH + 255) / 256, 256>>>(Wr[1], p_wrc + wstride);
    k_combW<HH><<<(NT * HH * HH + 255) / 256, 256>>>(Wr[2], p_wrc + 2 * wstride);
    k_combB<<<(NT * HH + 255) / 256, 256>>>(bb[0], p_bc);
    k_combB<<<(NT * HH + 255) / 256, 256>>>(bb[1], p_bc + NT * HH);
    k_combB<<<(NT * HH + 255) / 256, 256>>>(bb[2], p_bc + 2 * NT * HH);

    // layer-1 aggregation
    k_agg1<<<dim3(NN / 8, NREL), dim3(32, 8)>>>();

    const int NAGG = NREL * (NN / 8);          // 93750
    const int NFIN = NN / 2;                   // 25000

    // mega1: gemm L1 + agg L2
    k_mega<DIN, true, true, false><<<NT * GBLK + NAGG, 256>>>(
        0, x, Wl[0], p_wrc, p_bc, gam[0], bet[0], p_xs0, p_xbfB,
        nullptr, nullptr, nullptr);
    // mega2: gemm L2 + agg L3
    k_mega<HH, true, true, false><<<NT * GBLK + NAGG, 256>>>(
        1, p_xs0, Wl[1], p_wrc + wstride, p_bc + NT * HH, gam[1], bet[1],
        p_xs1, p_xbfA, nullptr, nullptr, nullptr);
    // mega3: gemm L3 + final FC/sigmoid
    k_mega<HH, false, false, true><<<NT * GBLK + NFIN, 256>>>(
        2, p_xs1, Wl[2], p_wrc + 2 * wstride, p_bc + 2 * NT * HH, gam[2], bet[2],
        p_xs0, nullptr, Wfc, bfc, out);
}

// round 9
// speedup vs baseline: 2.4669x; 2.4669x over previous
#include <cuda_runtime.h>
#include <cuda_bf16.h>
#include <math.h>
#include <stdint.h>

#define NT 9
#define NN 50000
#define NE 800000
#define NREL 15
#define DIN 64
#define HH 128

__device__ __constant__ int   c_src[NREL]   = {0,1,0,2,1,0,3,3,0,4,0,1,0,0,5};
__device__ __constant__ int   c_dst[NREL]   = {1,0,2,0,2,3,0,7,4,0,8,4,6,5,0};
__device__ __constant__ float c_invcnt[NT]  = {1.f/5.f,1.f,1.f/2.f,1.f,1.f/2.f,1.f,1.f,1.f,1.f};
__device__ __constant__ int   c_nseg[NT]    = {6,2,3,2,3,2,2,2,2};
__device__ __constant__ int   c_segrel[NT][6] = {
    {-1,1,3,6,9,14},{-1,0,0,0,0,0},{-1,2,4,0,0,0},{-1,5,0,0,0,0},
    {-1,8,11,0,0,0},{-1,13,0,0,0,0},{-1,12,0,0,0,0},{-1,7,0,0,0,0},{-1,10,0,0,0,0}};

// Scratch (device globals: allocation-free rule)
__device__ float g_xs0[(size_t)NT*NN*HH];
__device__ float g_xs1[(size_t)NT*NN*HH];
__device__ __nv_bfloat16 g_xbf[(size_t)NT*NN*HH];
__device__ float g_msgs[(size_t)NREL*NN*HH];
__device__ int   g_cnt[NREL*NN];
__device__ int   g_off[NREL*(NN+1)];
__device__ int   g_tmp[NREL*NN];
__device__ int   g_csrc[(size_t)NREL*NE];
__device__ float g_wrc[NT*HH*HH];
__device__ float g_bc[NT*HH];

// ---------------------------------------------------------------------------
// zero counters + convert input x to bf16 shadow
// ---------------------------------------------------------------------------
__global__ void k_cvt_zero(const float* __restrict__ x) {
    int i = blockIdx.x * blockDim.x + threadIdx.x;
    if (i < NREL * NN) g_cnt[i] = 0;
    if (i < NT * NN * DIN / 2) {
        float2 v = reinterpret_cast<const float2*>(x)[i];
        reinterpret_cast<__nv_bfloat162*>(g_xbf)[i] = __floats2bfloat162_rn(v.x, v.y);
    }
}

__global__ void k_hist(const int* __restrict__ edges) {
    int i = blockIdx.x * blockDim.x + threadIdx.x;
    if (i >= NREL * NE) return;
    int r = i / NE;
    int e = i - r * NE;
    int dst = edges[(size_t)r * 2 * NE + NE + e];
    atomicAdd(&g_cnt[r * NN + dst], 1);
}

__global__ void k_scan() {
    int r = blockIdx.x;
    int t = threadIdx.x;
    __shared__ int s[1024];
    int carry = 0;
    for (int base = 0; base < NN; base += 1024) {
        int i = base + t;
        int v = (i < NN) ? g_cnt[r * NN + i] : 0;
        s[t] = v;
        __syncthreads();
        #pragma unroll
        for (int d = 1; d < 1024; d <<= 1) {
            int x = (t >= d) ? s[t - d] : 0;
            __syncthreads();
            s[t] += x;
            __syncthreads();
        }
        int excl = carry + s[t] - v;
        if (i < NN) {
            g_off[r * (NN + 1) + i] = excl;
            g_tmp[r * NN + i] = excl;
        }
        carry += s[1023];
        __syncthreads();
    }
    if (t == 0) g_off[r * (NN + 1) + NN] = carry;
}

__global__ void k_fill(const int* __restrict__ edges) {
    int i = blockIdx.x * blockDim.x + threadIdx.x;
    if (i >= NREL * NE) return;
    int r = i / NE;
    int e = i - r * NE;
    int src = edges[(size_t)r * 2 * NE + e];
    int dst = edges[(size_t)r * 2 * NE + NE + e];
    int pos = atomicAdd(&g_tmp[r * NN + dst], 1);
    g_csrc[(size_t)r * NE + pos] = src;
}

// ---------------------------------------------------------------------------
// Combine Wr / b across relations sharing a dst type
// ---------------------------------------------------------------------------
template <int K>
__global__ void k_combW(const float* __restrict__ Wr) {
    int idx = blockIdx.x * blockDim.x + threadIdx.x;
    if (idx >= NT * K * HH) return;
    int i = idx / (K * HH);
    int j = idx - i * (K * HH);
    float s = 0.f;
    #pragma unroll
    for (int r = 0; r < NREL; r++)
        if (c_dst[r] == i) s += Wr[(size_t)r * K * HH + j];
    g_wrc[(size_t)i * K * HH + j] = s;
}

__global__ void k_combB(const float* __restrict__ b) {
    int idx = blockIdx.x * blockDim.x + threadIdx.x;
    if (idx >= NT * HH) return;
    int i = idx / HH;
    int j = idx - i * HH;
    float s = 0.f;
    #pragma unroll
    for (int r = 0; r < NREL; r++)
        if (c_dst[r] == i) s += b[r * HH + j];
    g_bc[i * HH + j] = s;
}

// ---------------------------------------------------------------------------
// bf16 gather aggregation: warp per dst row, 8 rows per block (32x8 threads).
// D=128: lane loads bf16x4 (8B); D=64: lane loads bf16x2 (4B).
// ---------------------------------------------------------------------------
template <int D>
__global__ void k_agg() {
    int r = blockIdx.y;
    int row = blockIdx.x * 8 + threadIdx.y;
    int t = threadIdx.x;                       // 0..31
    const __nv_bfloat16* __restrict__ xsrc = g_xbf + (size_t)c_src[r] * NN * D;
    float* __restrict__ msg = g_msgs + (size_t)r * NN * D;
    int o0 = g_off[r * (NN + 1) + row];
    int o1 = g_off[r * (NN + 1) + row + 1];
    const int* __restrict__ srcs = g_csrc + (size_t)r * NE;

    if (D == 128) {
        float ax[4] = {0.f, 0.f, 0.f, 0.f};
        float bx[4] = {0.f, 0.f, 0.f, 0.f};
        int e = o0;
        for (; e + 2 <= o1; e += 2) {
            int s0 = srcs[e], s1 = srcs[e + 1];
            uint2 u0 = *reinterpret_cast<const uint2*>(xsrc + (size_t)s0 * 128 + t * 4);
            uint2 u1 = *reinterpret_cast<const uint2*>(xsrc + (size_t)s1 * 128 + t * 4);
            float2 p0 = __bfloat1622float2(*reinterpret_cast<__nv_bfloat162*>(&u0.x));
            float2 p1 = __bfloat1622float2(*reinterpret_cast<__nv_bfloat162*>(&u0.y));
            float2 q0 = __bfloat1622float2(*reinterpret_cast<__nv_bfloat162*>(&u1.x));
            float2 q1 = __bfloat1622float2(*reinterpret_cast<__nv_bfloat162*>(&u1.y));
            ax[0] += p0.x; ax[1] += p0.y; ax[2] += p1.x; ax[3] += p1.y;
            bx[0] += q0.x; bx[1] += q0.y; bx[2] += q1.x; bx[3] += q1.y;
        }
        if (e < o1) {
            uint2 u0 = *reinterpret_cast<const uint2*>(xsrc + (size_t)srcs[e] * 128 + t * 4);
            float2 p0 = __bfloat1622float2(*reinterpret_cast<__nv_bfloat162*>(&u0.x));
            float2 p1 = __bfloat1622float2(*reinterpret_cast<__nv_bfloat162*>(&u0.y));
            ax[0] += p0.x; ax[1] += p0.y; ax[2] += p1.x; ax[3] += p1.y;
        }
        float inv = (o1 > o0) ? 1.f / (float)(o1 - o0) : 0.f;
        float4 o;
        o.x = (ax[0] + bx[0]) * inv; o.y = (ax[1] + bx[1]) * inv;
        o.z = (ax[2] + bx[2]) * inv; o.w = (ax[3] + bx[3]) * inv;
        *reinterpret_cast<float4*>(msg + (size_t)row * 128 + t * 4) = o;
    } else {
        float ax = 0.f, ay = 0.f, bxx = 0.f, byy = 0.f;
        int e = o0;
        for (; e + 2 <= o1; e += 2) {
            int s0 = srcs[e], s1 = srcs[e + 1];
            float2 p = __bfloat1622float2(*reinterpret_cast<const __nv_bfloat162*>(xsrc + (size_t)s0 * 64 + t * 2));
            float2 q = __bfloat1622float2(*reinterpret_cast<const __nv_bfloat162*>(xsrc + (size_t)s1 * 64 + t * 2));
            ax += p.x; ay += p.y; bxx += q.x; byy += q.y;
        }
        if (e < o1) {
            float2 p = __bfloat1622float2(*reinterpret_cast<const __nv_bfloat162*>(xsrc + (size_t)srcs[e] * 64 + t * 2));
            ax += p.x; ay += p.y;
        }
        float inv = (o1 > o0) ? 1.f / (float)(o1 - o0) : 0.f;
        float2 o = make_float2((ax + bxx) * inv, (ay + byy) * inv);
        *reinterpret_cast<float2*>(msg + (size_t)row * 64 + t * 2) = o;
    }
}

// ---------------------------------------------------------------------------
// TF32 mma. A fragments re-rounded with cvt.rna in registers; B raw-truncated.
// ---------------------------------------------------------------------------
__device__ __forceinline__ uint32_t f2tf32(float f) {
    uint32_t u;
    asm("cvt.rna.tf32.f32 %0, %1;" : "=r"(u) : "f"(f));
    return u;
}

__device__ __forceinline__ void mma_tf32(float* d, const uint32_t* a, const uint32_t* b) {
    asm volatile(
        "mma.sync.aligned.m16n8k8.row.col.f32.tf32.tf32.f32 "
        "{%0,%1,%2,%3}, {%4,%5,%6,%7}, {%8,%9}, {%0,%1,%2,%3};"
        : "+f"(d[0]), "+f"(d[1]), "+f"(d[2]), "+f"(d[3])
        : "r"(a[0]), "r"(a[1]), "r"(a[2]), "r"(a[3]), "r"(b[0]), "r"(b[1]));
}

__device__ __forceinline__ void cp16(uint32_t dst, const void* src) {
    asm volatile("cp.async.cg.shared.global [%0], [%1], 16;" :: "r"(dst), "l"(src));
}

#define APAD 36
#define BPAD 136
#define ATILE (128 * APAD)
#define BTILE (32 * BPAD)
#define GSMEM ((2 * ATILE + 2 * BTILE) * 4)

// ---------------------------------------------------------------------------
// Segmented TF32 GEMM + fused leaky-ReLU + LayerNorm, cp.async double-buffered.
// grid (GBLK, NT); BM=128, BK=32, 8 warps, warp tile 16x128.
// ---------------------------------------------------------------------------
template <int SK, bool WRITEBF>
__global__ void __launch_bounds__(256) k_gemm_ln(const float* __restrict__ xin,
                                                const float* __restrict__ Wl,
                                                const float* __restrict__ gam,
                                                const float* __restrict__ bet,
                                                float* __restrict__ out) {
    extern __shared__ uint32_t smem[];
    uint32_t* sA = smem;                  // 2 x ATILE
    uint32_t* sB = smem + 2 * ATILE;      // 2 x BTILE

    int tid = threadIdx.x;
    int lane = tid & 31;
    int w = tid >> 5;
    int type = blockIdx.y;
    int r0 = blockIdx.x * 128;

    uint32_t sAu = (uint32_t)__cvta_generic_to_shared(sA);
    uint32_t sBu = (uint32_t)__cvta_generic_to_shared(sB);

    constexpr int CH = SK / 32;
    int nchunk = c_nseg[type] * CH;

    auto issue = [&](int c, int buf) {
        int seg = c / CH;
        int off = (c - seg * CH) * 32;
        int rel = c_segrel[type][seg];
        const float* Ab = (seg == 0) ? xin + (size_t)type * NN * SK
                                     : g_msgs + (size_t)rel * NN * SK;
        const float* Bb = (seg == 0) ? g_wrc + (size_t)type * SK * HH
                                     : Wl + (size_t)rel * SK * HH;
        uint32_t dA = sAu + (uint32_t)buf * ATILE * 4;
        uint32_t dB = sBu + (uint32_t)buf * BTILE * 4;
        #pragma unroll
        for (int l = 0; l < 4; l++) {
            int f = tid + l * 256;
            int row = f >> 3;
            int c0 = (f & 7) * 4;
            int grow = r0 + row;
            if (grow > NN - 1) grow = NN - 1;   // clamp: junk rows masked at epilogue
            cp16(dA + (uint32_t)(row * APAD + c0) * 4,
                 Ab + (size_t)grow * SK + off + c0);
        }
        #pragma unroll
        for (int l = 0; l < 4; l++) {
            int f = tid + l * 256;
            int krow = f >> 5;
            int n0 = (f & 31) * 4;
            cp16(dB + (uint32_t)(krow * BPAD + n0) * 4,
                 Bb + (size_t)(off + krow) * HH + n0);
        }
        asm volatile("cp.async.commit_group;");
    };

    float acc[16][4];
    #pragma unroll
    for (int nt = 0; nt < 16; nt++)
        #pragma unroll
        for (int j = 0; j < 4; j++) acc[nt][j] = 0.f;

    issue(0, 0);
    for (int c = 0; c < nchunk; c++) {
        int buf = c & 1;
        if (c + 1 < nchunk) {
            issue(c + 1, buf ^ 1);
            asm volatile("cp.async.wait_group 1;");
        } else {
            asm volatile("cp.async.wait_group 0;");
        }
        __syncthreads();
        const uint32_t* cA = sA + buf * ATILE;
        const uint32_t* cB = sB + buf * BTILE;
        #pragma unroll
        for (int kt = 0; kt < 4; kt++) {
            int abase = (w * 16 + (lane >> 2)) * APAD + kt * 8 + (lane & 3);
            uint32_t af[4];
            af[0] = f2tf32(__uint_as_float(cA[abase]));
            af[1] = f2tf32(__uint_as_float(cA[abase + 8 * APAD]));
            af[2] = f2tf32(__uint_as_float(cA[abase + 4]));
            af[3] = f2tf32(__uint_as_float(cA[abase + 8 * APAD + 4]));
            int bb = (kt * 8 + (lane & 3)) * BPAD + (lane >> 2);
            #pragma unroll
            for (int nt = 0; nt < 16; nt++) {
                uint32_t bf[2];
                bf[0] = cB[bb + nt * 8];
                bf[1] = cB[bb + nt * 8 + 4 * BPAD];
                mma_tf32(acc[nt], af, bf);
            }
        }
        __syncthreads();
    }

    // ---- fused epilogue: bias, relation-mean, leaky ReLU, LayerNorm ----
    float inv = c_invcnt[type];
    #pragma unroll
    for (int h = 0; h < 2; h++) {
        int row = r0 + w * 16 + (lane >> 2) + h * 8;
        float v[16][2];
        float s = 0.f;
        #pragma unroll
        for (int nt = 0; nt < 16; nt++) {
            int col = nt * 8 + (lane & 3) * 2;
            float x0 = (acc[nt][2 * h] + g_bc[type * HH + col]) * inv;
            float x1 = (acc[nt][2 * h + 1] + g_bc[type * HH + col + 1]) * inv;
            x0 = (x0 >= 0.f) ? x0 : 0.01f * x0;
            x1 = (x1 >= 0.f) ? x1 : 0.01f * x1;
            v[nt][0] = x0; v[nt][1] = x1;
            s += x0 + x1;
        }
        s += __shfl_xor_sync(0xffffffffu, s, 1);
        s += __shfl_xor_sync(0xffffffffu, s, 2);
        float mu = s * (1.f / HH);
        float q = 0.f;
        #pragma unroll
        for (int nt = 0; nt < 16; nt++) {
            float d0 = v[nt][0] - mu, d1 = v[nt][1] - mu;
            v[nt][0] = d0; v[nt][1] = d1;
            q += d0 * d0 + d1 * d1;
        }
        q += __shfl_xor_sync(0xffffffffu, q, 1);
        q += __shfl_xor_sync(0xffffffffu, q, 2);
        float rs = rsqrtf(q * (1.f / HH) + 1e-5f);
        if (row < NN) {
            float* op = out + (size_t)type * NN * HH + (size_t)row * HH;
            __nv_bfloat16* obf = g_xbf + (size_t)type * NN * HH + (size_t)row * HH;
            #pragma unroll
            for (int nt = 0; nt < 16; nt++) {
                int col = nt * 8 + (lane & 3) * 2;
                float2 o;
                o.x = v[nt][0] * rs * gam[col] + bet[col];
                o.y = v[nt][1] * rs * gam[col + 1] + bet[col + 1];
                *reinterpret_cast<float2*>(op + col) = o;
                if (WRITEBF)
                    *reinterpret_cast<__nv_bfloat162*>(obf + col) =
                        __floats2bfloat162_rn(o.x, o.y);
            }
        }
    }
}

// ---------------------------------------------------------------------------
// Final: concat(9 types) @ Wfc + bfc, sigmoid
// ---------------------------------------------------------------------------
__device__ __forceinline__ float blockSum128(float v, float* sh) {
    #pragma unroll
    for (int o = 16; o > 0; o >>= 1) v += __shfl_xor_sync(0xffffffffu, v, o);
    int w = threadIdx.x >> 5;
    if ((threadIdx.x & 31) == 0) sh[w] = v;
    __syncthreads();
    float tot = sh[0] + sh[1] + sh[2] + sh[3];
    __syncthreads();
    return tot;
}

__global__ void k_final(const float* __restrict__ xs, const float* __restrict__ Wfc,
                        const float* __restrict__ bfc, float* __restrict__ out) {
    __shared__ float sh[4];
    int n = blockIdx.x;
    int t = threadIdx.x;
    float p = 0.f;
    #pragma unroll
    for (int i = 0; i < NT; i++)
        p += xs[((size_t)i * NN + n) * HH + t] * Wfc[i * HH + t];
    float tot = blockSum128(p, sh);
    if (t == 0) out[n] = 1.f / (1.f + expf(-(tot + bfc[0])));
}

// ---------------------------------------------------------------------------
// Host driver (single stream, serial)
// ---------------------------------------------------------------------------
template <int SK, bool WBF>
static void run_layer(const float* xin, const float* Wl, const float* Wr,
                      const float* b, const float* gam, const float* bet,
                      float* out) {
    dim3 ga(NN / 8, NREL);
    k_agg<SK><<<ga, dim3(32, 8)>>>();          // 32 lanes per row, both D
    k_combW<SK><<<(NT * SK * HH + 255) / 256, 256>>>(Wr);
    k_combB<<<(NT * HH + 255) / 256, 256>>>(b);
    dim3 gg((NN + 127) / 128, NT);
    k_gemm_ln<SK, WBF><<<gg, 256, GSMEM>>>(xin, Wl, gam, bet, out);
}

extern "C" void kernel_launch(void* const* d_in, const int* in_sizes, int n_in,
                              void* d_out, int out_size) {
    const float* x    = (const float*)d_in[0];
    const int* edges  = (const int*)d_in[1];
    const float* Wl1  = (const float*)d_in[2];
    const float* Wr1  = (const float*)d_in[3];
    const float* b1   = (const float*)d_in[4];
    const float* Wl2  = (const float*)d_in[5];
    const float* Wr2  = (const float*)d_in[6];
    const float* b2   = (const float*)d_in[7];
    const float* Wl3  = (const float*)d_in[8];
    const float* Wr3  = (const float*)d_in[9];
    const float* b3   = (const float*)d_in[10];
    const float* g1   = (const float*)d_in[11];
    const float* be1  = (const float*)d_in[12];
    const float* g2   = (const float*)d_in[13];
    const float* be2  = (const float*)d_in[14];
    const float* g3   = (const float*)d_in[15];
    const float* be3  = (const float*)d_in[16];
    const float* Wfc  = (const float*)d_in[17];
    const float* bfc  = (const float*)d_in[18];
    float* out = (float*)d_out;

    float *p_xs0, *p_xs1;
    cudaGetSymbolAddress((void**)&p_xs0, g_xs0);
    cudaGetSymbolAddress((void**)&p_xs1, g_xs1);

    cudaFuncSetAttribute(k_gemm_ln<DIN, true>,
                         cudaFuncAttributeMaxDynamicSharedMemorySize, GSMEM);
    cudaFuncSetAttribute(k_gemm_ln<HH, true>,
                         cudaFuncAttributeMaxDynamicSharedMemorySize, GSMEM);
    cudaFuncSetAttribute(k_gemm_ln<HH, false>,
                         cudaFuncAttributeMaxDynamicSharedMemorySize, GSMEM);

    k_cvt_zero<<<(NT * NN * DIN / 2 + 255) / 256, 256>>>(x);
    k_hist<<<(NREL * NE + 255) / 256, 256>>>(edges);
    k_scan<<<NREL, 1024>>>();
    k_fill<<<(NREL * NE + 255) / 256, 256>>>(edges);

    run_layer<DIN, true>(x,     Wl1, Wr1, b1, g1, be1, p_xs0);
    run_layer<HH,  true>(p_xs0, Wl2, Wr2, b2, g2, be2, p_xs1);
    run_layer<HH, false>(p_xs1, Wl3, Wr3, b3, g3, be3, p_xs0);

    k_final<<<NN, HH>>>(p_xs0, Wfc, bfc, out);
}

// round 10
// speedup vs baseline: 2.4899x; 1.0093x over previous
#include <cuda_runtime.h>
#include <cuda_bf16.h>
#include <math.h>
#include <stdint.h>

#define NT 9
#define NN 50000
#define NE 800000
#define NREL 15
#define DIN 64
#define HH 128

__device__ __constant__ int   c_src[NREL]   = {0,1,0,2,1,0,3,3,0,4,0,1,0,0,5};
__device__ __constant__ int   c_dst[NREL]   = {1,0,2,0,2,3,0,7,4,0,8,4,6,5,0};
__device__ __constant__ float c_invcnt[NT]  = {1.f/5.f,1.f,1.f/2.f,1.f,1.f/2.f,1.f,1.f,1.f,1.f};
__device__ __constant__ int   c_nseg[NT]    = {6,2,3,2,3,2,2,2,2};
__device__ __constant__ int   c_segrel[NT][6] = {
    {-1,1,3,6,9,14},{-1,0,0,0,0,0},{-1,2,4,0,0,0},{-1,5,0,0,0,0},
    {-1,8,11,0,0,0},{-1,13,0,0,0,0},{-1,12,0,0,0,0},{-1,7,0,0,0,0},{-1,10,0,0,0,0}};

// Scratch (device globals: allocation-free rule)
__device__ float g_xs0[(size_t)NT*NN*HH];
__device__ float g_xs1[(size_t)NT*NN*HH];
__device__ __nv_bfloat16 g_xbf[(size_t)NT*NN*HH];
__device__ float g_msgs[(size_t)NREL*NN*HH];
__device__ int   g_cnt[NREL*NN];
__device__ int   g_off[NREL*(NN+1)];
__device__ int   g_tmp[NREL*NN];
__device__ int   g_csrc[(size_t)NREL*NE];
__device__ float g_wrc[3ull*NT*HH*HH];
__device__ float g_bc[3*NT*HH];

// ---------------------------------------------------------------------------
// hist (g_cnt pre-zeroed by cudaMemsetAsync) + bf16 shadow convert, fused
// ---------------------------------------------------------------------------
__global__ void k_hist_cvt(const int* __restrict__ edges, const float* __restrict__ x) {
    int i = blockIdx.x * blockDim.x + threadIdx.x;
    if (i < NREL * NE) {
        int r = i / NE;
        int e = i - r * NE;
        int dst = edges[(size_t)r * 2 * NE + NE + e];
        atomicAdd(&g_cnt[r * NN + dst], 1);
    }
    if (i < NT * NN * DIN / 2) {
        float2 v = reinterpret_cast<const float2*>(x)[i];
        reinterpret_cast<__nv_bfloat162*>(g_xbf)[i] = __floats2bfloat162_rn(v.x, v.y);
    }
}

__global__ void k_scan() {
    int r = blockIdx.x;
    int t = threadIdx.x;
    __shared__ int s[1024];
    int carry = 0;
    for (int base = 0; base < NN; base += 1024) {
        int i = base + t;
        int v = (i < NN) ? g_cnt[r * NN + i] : 0;
        s[t] = v;
        __syncthreads();
        #pragma unroll
        for (int d = 1; d < 1024; d <<= 1) {
            int x = (t >= d) ? s[t - d] : 0;
            __syncthreads();
            s[t] += x;
            __syncthreads();
        }
        int excl = carry + s[t] - v;
        if (i < NN) {
            g_off[r * (NN + 1) + i] = excl;
            g_tmp[r * NN + i] = excl;
        }
        carry += s[1023];
        __syncthreads();
    }
    if (t == 0) g_off[r * (NN + 1) + NN] = carry;
}

__global__ void k_fill(const int* __restrict__ edges) {
    int i = blockIdx.x * blockDim.x + threadIdx.x;
    if (i >= NREL * NE) return;
    int r = i / NE;
    int e = i - r * NE;
    int src = edges[(size_t)r * 2 * NE + e];
    int dst = edges[(size_t)r * 2 * NE + NE + e];
    int pos = atomicAdd(&g_tmp[r * NN + dst], 1);
    g_csrc[(size_t)r * NE + pos] = src;
}

// ---------------------------------------------------------------------------
// Combine Wr / b across relations sharing a dst type (per-layer banks)
// ---------------------------------------------------------------------------
template <int K>
__global__ void k_combW(const float* __restrict__ Wr, float* __restrict__ wrc) {
    int idx = blockIdx.x * blockDim.x + threadIdx.x;
    if (idx >= NT * K * HH) return;
    int i = idx / (K * HH);
    int j = idx - i * (K * HH);
    float s = 0.f;
    #pragma unroll
    for (int r = 0; r < NREL; r++)
        if (c_dst[r] == i) s += Wr[(size_t)r * K * HH + j];
    wrc[(size_t)i * K * HH + j] = s;
}

__global__ void k_combB(const float* __restrict__ b, float* __restrict__ bc) {
    int idx = blockIdx.x * blockDim.x + threadIdx.x;
    if (idx >= NT * HH) return;
    int i = idx / HH;
    int j = idx - i * HH;
    float s = 0.f;
    #pragma unroll
    for (int r = 0; r < NREL; r++)
        if (c_dst[r] == i) s += b[r * HH + j];
    bc[i * HH + j] = s;
}

// ---------------------------------------------------------------------------
// bf16 gather aggregation, deep-MLP layout. Warp per dst row, 8 rows/block.
// D=128: half-warp covers the 256B row (16B/lane), 4 edges in flight.
// D=64 : quarter-warp covers the 128B row (16B/lane), 8 edges in flight.
// ---------------------------------------------------------------------------
__device__ __forceinline__ void acc8(float* a, uint4 u) {
    float2 p0 = __bfloat1622float2(*reinterpret_cast<__nv_bfloat162*>(&u.x));
    float2 p1 = __bfloat1622float2(*reinterpret_cast<__nv_bfloat162*>(&u.y));
    float2 p2 = __bfloat1622float2(*reinterpret_cast<__nv_bfloat162*>(&u.z));
    float2 p3 = __bfloat1622float2(*reinterpret_cast<__nv_bfloat162*>(&u.w));
    a[0] += p0.x; a[1] += p0.y; a[2] += p1.x; a[3] += p1.y;
    a[4] += p2.x; a[5] += p2.y; a[6] += p3.x; a[7] += p3.y;
}

template <int D>
__global__ void k_agg() {
    int r = blockIdx.y;
    int row = blockIdx.x * 8 + (threadIdx.x >> 5);
    int lane = threadIdx.x & 31;
    const uint4* __restrict__ base =
        reinterpret_cast<const uint4*>(g_xbf + (size_t)c_src[r] * NN * D);
    float* __restrict__ msg = g_msgs + (size_t)r * NN * D;
    int o0 = g_off[r * (NN + 1) + row];
    int o1 = g_off[r * (NN + 1) + row + 1];
    const int* __restrict__ srcs = g_csrc + (size_t)r * NE;
    float inv = (o1 > o0) ? 1.f / (float)(o1 - o0) : 0.f;

    float a[8] = {0.f, 0.f, 0.f, 0.f, 0.f, 0.f, 0.f, 0.f};

    if (D == 128) {
        int half = lane >> 4, sub = lane & 15;     // row stride = 16 uint4
        int e = o0;
        for (; e + 4 <= o1; e += 4) {
            int s0 = srcs[e + half];
            int s1 = srcs[e + 2 + half];
            uint4 u0 = base[(size_t)s0 * 16 + sub];
            uint4 u1 = base[(size_t)s1 * 16 + sub];
            acc8(a, u0); acc8(a, u1);
        }
        if (e + 2 <= o1) {
            uint4 u0 = base[(size_t)srcs[e + half] * 16 + sub];
            acc8(a, u0);
            e += 2;
        }
        if (e < o1 && half == 0) {
            uint4 u0 = base[(size_t)srcs[e] * 16 + sub];
            acc8(a, u0);
        }
        #pragma unroll
        for (int k = 0; k < 8; k++)
            a[k] += __shfl_down_sync(0xffffffffu, a[k], 16);
        if (half == 0) {
            float* mp = msg + (size_t)row * 128 + sub * 8;
            float4 v0 = make_float4(a[0] * inv, a[1] * inv, a[2] * inv, a[3] * inv);
            float4 v1 = make_float4(a[4] * inv, a[5] * inv, a[6] * inv, a[7] * inv);
            reinterpret_cast<float4*>(mp)[0] = v0;
            reinterpret_cast<float4*>(mp)[1] = v1;
        }
    } else {
        int q = lane >> 3, sub = lane & 7;         // row stride = 8 uint4
        int e = o0;
        for (; e + 8 <= o1; e += 8) {
            int s0 = srcs[e + q];
            int s1 = srcs[e + 4 + q];
            uint4 u0 = base[(size_t)s0 * 8 + sub];
            uint4 u1 = base[(size_t)s1 * 8 + sub];
            acc8(a, u0); acc8(a, u1);
        }
        if (e + 4 <= o1) {
            uint4 u0 = base[(size_t)srcs[e + q] * 8 + sub];
            acc8(a, u0);
            e += 4;
        }
        int rem = o1 - e;
        if (q < rem) {
            uint4 u0 = base[(size_t)srcs[e + q] * 8 + sub];
            acc8(a, u0);
        }
        #pragma unroll
        for (int k = 0; k < 8; k++) {
            a[k] += __shfl_down_sync(0xffffffffu, a[k], 16);
            a[k] += __shfl_down_sync(0xffffffffu, a[k], 8);
        }
        if (lane < 8) {
            float* mp = msg + (size_t)row * 64 + sub * 8;
            float4 v0 = make_float4(a[0] * inv, a[1] * inv, a[2] * inv, a[3] * inv);
            float4 v1 = make_float4(a[4] * inv, a[5] * inv, a[6] * inv, a[7] * inv);
            reinterpret_cast<float4*>(mp)[0] = v0;
            reinterpret_cast<float4*>(mp)[1] = v1;
        }
    }
}

// ---------------------------------------------------------------------------
// TF32 mma. A fragments re-rounded with cvt.rna in registers; B raw-truncated.
// ---------------------------------------------------------------------------
__device__ __forceinline__ uint32_t f2tf32(float f) {
    uint32_t u;
    asm("cvt.rna.tf32.f32 %0, %1;" : "=r"(u) : "f"(f));
    return u;
}

__device__ __forceinline__ void mma_tf32(float* d, const uint32_t* a, const uint32_t* b) {
    asm volatile(
        "mma.sync.aligned.m16n8k8.row.col.f32.tf32.tf32.f32 "
        "{%0,%1,%2,%3}, {%4,%5,%6,%7}, {%8,%9}, {%0,%1,%2,%3};"
        : "+f"(d[0]), "+f"(d[1]), "+f"(d[2]), "+f"(d[3])
        : "r"(a[0]), "r"(a[1]), "r"(a[2]), "r"(a[3]), "r"(b[0]), "r"(b[1]));
}

__device__ __forceinline__ void cp16(uint32_t dst, const void* src) {
    asm volatile("cp.async.cg.shared.global [%0], [%1], 16;" :: "r"(dst), "l"(src));
}

#define APAD 36
#define BPAD 136
#define ATILE (128 * APAD)
#define BTILE (32 * BPAD)
#define GSMEM ((2 * ATILE + 2 * BTILE) * 4)

// ---------------------------------------------------------------------------
// Segmented TF32 GEMM + fused leaky-ReLU + LayerNorm, cp.async double-buffered.
// grid (GBLK, NT); BM=128, BK=32, 8 warps, warp tile 16x128.
// ---------------------------------------------------------------------------
template <int SK, bool WRITEBF>
__global__ void __launch_bounds__(256) k_gemm_ln(const float* __restrict__ xin,
                                                const float* __restrict__ Wl,
                                                const float* __restrict__ wrc,
                                                const float* __restrict__ bc,
                                                const float* __restrict__ gam,
                                                const float* __restrict__ bet,
                                                float* __restrict__ out) {
    extern __shared__ uint32_t smem[];
    uint32_t* sA = smem;                  // 2 x ATILE
    uint32_t* sB = smem + 2 * ATILE;      // 2 x BTILE

    int tid = threadIdx.x;
    int lane = tid & 31;
    int w = tid >> 5;
    int type = blockIdx.y;
    int r0 = blockIdx.x * 128;

    uint32_t sAu = (uint32_t)__cvta_generic_to_shared(sA);
    uint32_t sBu = (uint32_t)__cvta_generic_to_shared(sB);

    constexpr int CH = SK / 32;
    int nchunk = c_nseg[type] * CH;

    auto issue = [&](int c, int buf) {
        int seg = c / CH;
        int off = (c - seg * CH) * 32;
        int rel = c_segrel[type][seg];
        const float* Ab = (seg == 0) ? xin + (size_t)type * NN * SK
                                     : g_msgs + (size_t)rel * NN * SK;
        const float* Bb = (seg == 0) ? wrc + (size_t)type * SK * HH
                                     : Wl + (size_t)rel * SK * HH;
        uint32_t dA = sAu + (uint32_t)buf * ATILE * 4;
        uint32_t dB = sBu + (uint32_t)buf * BTILE * 4;
        #pragma unroll
        for (int l = 0; l < 4; l++) {
            int f = tid + l * 256;
            int row = f >> 3;
            int c0 = (f & 7) * 4;
            int grow = r0 + row;
            if (grow > NN - 1) grow = NN - 1;   // clamp: junk rows masked at epilogue
            cp16(dA + (uint32_t)(row * APAD + c0) * 4,
                 Ab + (size_t)grow * SK + off + c0);
        }
        #pragma unroll
        for (int l = 0; l < 4; l++) {
            int f = tid + l * 256;
            int krow = f >> 5;
            int n0 = (f & 31) * 4;
            cp16(dB + (uint32_t)(krow * BPAD + n0) * 4,
                 Bb + (size_t)(off + krow) * HH + n0);
        }
        asm volatile("cp.async.commit_group;");
    };

    float acc[16][4];
    #pragma unroll
    for (int nt = 0; nt < 16; nt++)
        #pragma unroll
        for (int j = 0; j < 4; j++) acc[nt][j] = 0.f;

    issue(0, 0);
    for (int c = 0; c < nchunk; c++) {
        int buf = c & 1;
        if (c + 1 < nchunk) {
            issue(c + 1, buf ^ 1);
            asm volatile("cp.async.wait_group 1;");
        } else {
            asm volatile("cp.async.wait_group 0;");
        }
        __syncthreads();
        const uint32_t* cA = sA + buf * ATILE;
        const uint32_t* cB = sB + buf * BTILE;
        #pragma unroll
        for (int kt = 0; kt < 4; kt++) {
            int abase = (w * 16 + (lane >> 2)) * APAD + kt * 8 + (lane & 3);
            uint32_t af[4];
            af[0] = f2tf32(__uint_as_float(cA[abase]));
            af[1] = f2tf32(__uint_as_float(cA[abase + 8 * APAD]));
            af[2] = f2tf32(__uint_as_float(cA[abase + 4]));
            af[3] = f2tf32(__uint_as_float(cA[abase + 8 * APAD + 4]));
            int bb = (kt * 8 + (lane & 3)) * BPAD + (lane >> 2);
            #pragma unroll
            for (int nt = 0; nt < 16; nt++) {
                uint32_t bf[2];
                bf[0] = cB[bb + nt * 8];
                bf[1] = cB[bb + nt * 8 + 4 * BPAD];
                mma_tf32(acc[nt], af, bf);
            }
        }
        __syncthreads();
    }

    // ---- fused epilogue: bias, relation-mean, leaky ReLU, LayerNorm ----
    float inv = c_invcnt[type];
    #pragma unroll
    for (int h = 0; h < 2; h++) {
        int row = r0 + w * 16 + (lane >> 2) + h * 8;
        float v[16][2];
        float s = 0.f;
        #pragma unroll
        for (int nt = 0; nt < 16; nt++) {
            int col = nt * 8 + (lane & 3) * 2;
            float x0 = (acc[nt][2 * h] + bc[type * HH + col]) * inv;
            float x1 = (acc[nt][2 * h + 1] + bc[type * HH + col + 1]) * inv;
            x0 = (x0 >= 0.f) ? x0 : 0.01f * x0;
            x1 = (x1 >= 0.f) ? x1 : 0.01f * x1;
            v[nt][0] = x0; v[nt][1] = x1;
            s += x0 + x1;
        }
        s += __shfl_xor_sync(0xffffffffu, s, 1);
        s += __shfl_xor_sync(0xffffffffu, s, 2);
        float mu = s * (1.f / HH);
        float q = 0.f;
        #pragma unroll
        for (int nt = 0; nt < 16; nt++) {
            float d0 = v[nt][0] - mu, d1 = v[nt][1] - mu;
            v[nt][0] = d0; v[nt][1] = d1;
            q += d0 * d0 + d1 * d1;
        }
        q += __shfl_xor_sync(0xffffffffu, q, 1);
        q += __shfl_xor_sync(0xffffffffu, q, 2);
        float rs = rsqrtf(q * (1.f / HH) + 1e-5f);
        if (row < NN) {
            float* op = out + (size_t)type * NN * HH + (size_t)row * HH;
            __nv_bfloat16* obf = g_xbf + (size_t)type * NN * HH + (size_t)row * HH;
            #pragma unroll
            for (int nt = 0; nt < 16; nt++) {
                int col = nt * 8 + (lane & 3) * 2;
                float2 o;
                o.x = v[nt][0] * rs * gam[col] + bet[col];
                o.y = v[nt][1] * rs * gam[col + 1] + bet[col + 1];
                *reinterpret_cast<float2*>(op + col) = o;
                if (WRITEBF)
                    *reinterpret_cast<__nv_bfloat162*>(obf + col) =
                        __floats2bfloat162_rn(o.x, o.y);
            }
        }
    }
}

// ---------------------------------------------------------------------------
// Final: concat(9 types) @ Wfc + bfc, sigmoid
// ---------------------------------------------------------------------------
__device__ __forceinline__ float blockSum128(float v, float* sh) {
    #pragma unroll
    for (int o = 16; o > 0; o >>= 1) v += __shfl_xor_sync(0xffffffffu, v, o);
    int w = threadIdx.x >> 5;
    if ((threadIdx.x & 31) == 0) sh[w] = v;
    __syncthreads();
    float tot = sh[0] + sh[1] + sh[2] + sh[3];
    __syncthreads();
    return tot;
}

__global__ void k_final(const float* __restrict__ xs, const float* __restrict__ Wfc,
                        const float* __restrict__ bfc, float* __restrict__ out) {
    __shared__ float sh[4];
    int n = blockIdx.x;
    int t = threadIdx.x;
    float p = 0.f;
    #pragma unroll
    for (int i = 0; i < NT; i++)
        p += xs[((size_t)i * NN + n) * HH + t] * Wfc[i * HH + t];
    float tot = blockSum128(p, sh);
    if (t == 0) out[n] = 1.f / (1.f + expf(-(tot + bfc[0])));
}

// ---------------------------------------------------------------------------
// Host driver (single stream, serial)
// ---------------------------------------------------------------------------
extern "C" void kernel_launch(void* const* d_in, const int* in_sizes, int n_in,
                              void* d_out, int out_size) {
    const float* x    = (const float*)d_in[0];
    const int* edges  = (const int*)d_in[1];
    const float* Wl1  = (const float*)d_in[2];
    const float* Wr1  = (const float*)d_in[3];
    const float* b1   = (const float*)d_in[4];
    const float* Wl2  = (const float*)d_in[5];
    const float* Wr2  = (const float*)d_in[6];
    const float* b2   = (const float*)d_in[7];
    const float* Wl3  = (const float*)d_in[8];
    const float* Wr3  = (const float*)d_in[9];
    const float* b3   = (const float*)d_in[10];
    const float* g1   = (const float*)d_in[11];
    const float* be1  = (const float*)d_in[12];
    const float* g2   = (const float*)d_in[13];
    const float* be2  = (const float*)d_in[14];
    const float* g3   = (const float*)d_in[15];
    const float* be3  = (const float*)d_in[16];
    const float* Wfc  = (const float*)d_in[17];
    const float* bfc  = (const float*)d_in[18];
    float* out = (float*)d_out;

    float *p_xs0, *p_xs1, *p_wrc, *p_bc;
    int* p_cnt;
    cudaGetSymbolAddress((void**)&p_xs0, g_xs0);
    cudaGetSymbolAddress((void**)&p_xs1, g_xs1);
    cudaGetSymbolAddress((void**)&p_wrc, g_wrc);
    cudaGetSymbolAddress((void**)&p_bc, g_bc);
    cudaGetSymbolAddress((void**)&p_cnt, g_cnt);

    cudaFuncSetAttribute(k_gemm_ln<DIN, true>,
                         cudaFuncAttributeMaxDynamicSharedMemorySize, GSMEM);
    cudaFuncSetAttribute(k_gemm_ln<HH, true>,
                         cudaFuncAttributeMaxDynamicSharedMemorySize, GSMEM);
    cudaFuncSetAttribute(k_gemm_ln<HH, false>,
                         cudaFuncAttributeMaxDynamicSharedMemorySize, GSMEM);

    size_t wstride = (size_t)NT * HH * HH;

    // CSR build chain (g_cnt zeroed via async memset — graph-capturable)
    cudaMemsetAsync(p_cnt, 0, (size_t)NREL * NN * sizeof(int));
    k_hist_cvt<<<(NT * NN * DIN / 2 + 255) / 256, 256>>>(edges, x);
    k_scan<<<NREL, 1024>>>();
    k_fill<<<(NREL * NE + 255) / 256, 256>>>(edges);

    // layer-1 aggregation (launch #4 for ncu)
    k_agg<DIN><<<dim3(NN / 8, NREL), 256>>>();

    // weight prep (all layers)
    k_combW<DIN><<<(NT * DIN * HH + 255) / 256, 256>>>(Wr1, p_wrc);
    k_combW<HH><<<(NT * HH * HH + 255) / 256, 256>>>(Wr2, p_wrc + wstride);
    k_combW<HH><<<(NT * HH * HH + 255) / 256, 256>>>(Wr3, p_wrc + 2 * wstride);
    k_combB<<<(NT * HH + 255) / 256, 256>>>(b1, p_bc);
    k_combB<<<(NT * HH + 255) / 256, 256>>>(b2, p_bc + NT * HH);
    k_combB<<<(NT * HH + 255) / 256, 256>>>(b3, p_bc + 2 * NT * HH);

    dim3 gg((NN + 127) / 128, NT);
    dim3 ga(NN / 8, NREL);

    // layer 1
    k_gemm_ln<DIN, true><<<gg, 256, GSMEM>>>(x, Wl1, p_wrc, p_bc, g1, be1, p_xs0);
    // layer 2
    k_agg<HH><<<ga, 256>>>();
    k_gemm_ln<HH, true><<<gg, 256, GSMEM>>>(p_xs0, Wl2, p_wrc + wstride,
                                            p_bc + NT * HH, g2, be2, p_xs1);
    // layer 3
    k_agg<HH><<<ga, 256>>>();
    k_gemm_ln<HH, false><<<gg, 256, GSMEM>>>(p_xs1, Wl3, p_wrc + 2 * wstride,
                                             p_bc + 2 * NT * HH, g3, be3, p_xs0);

    k_final<<<NN, HH>>>(p_xs0, Wfc, bfc, out);
}

// round 11
// speedup vs baseline: 2.5098x; 1.0080x over previous
#include <cuda_runtime.h>
#include <cuda_bf16.h>
#include <math.h>
#include <stdint.h>

#define NT 9
#define NN 50000
#define NE 800000
#define NREL 15
#define DIN 64
#define HH 128

__device__ __constant__ int   c_src[NREL]   = {0,1,0,2,1,0,3,3,0,4,0,1,0,0,5};
__device__ __constant__ int   c_dst[NREL]   = {1,0,2,0,2,3,0,7,4,0,8,4,6,5,0};
__device__ __constant__ float c_invcnt[NT]  = {1.f/5.f,1.f,1.f/2.f,1.f,1.f/2.f,1.f,1.f,1.f,1.f};
__device__ __constant__ int   c_nseg[NT]    = {6,2,3,2,3,2,2,2,2};
__device__ __constant__ int   c_segrel[NT][6] = {
    {-1,1,3,6,9,14},{-1,0,0,0,0,0},{-1,2,4,0,0,0},{-1,5,0,0,0,0},
    {-1,8,11,0,0,0},{-1,13,0,0,0,0},{-1,12,0,0,0,0},{-1,7,0,0,0,0},{-1,10,0,0,0,0}};

// Scratch (device globals: allocation-free rule)
__device__ float g_xs0[(size_t)NT*NN*HH];
__device__ float g_xs1[(size_t)NT*NN*HH];
__device__ __nv_bfloat16 g_xbf[(size_t)NT*NN*HH];
__device__ float g_msgs[(size_t)NREL*NN*HH];
__device__ int   g_cnt[NREL*NN];
__device__ int   g_off[NREL*(NN+1)];
__device__ int   g_tmp[NREL*NN];
__device__ int   g_csrc[(size_t)NREL*NE];
__device__ float g_wrc[3ull*NT*HH*HH];
__device__ float g_bc[3*NT*HH];

// ---------------------------------------------------------------------------
// hist (g_cnt pre-zeroed by cudaMemsetAsync) + bf16 shadow convert, fused
// ---------------------------------------------------------------------------
__global__ void k_hist_cvt(const int* __restrict__ edges, const float* __restrict__ x) {
    int i = blockIdx.x * blockDim.x + threadIdx.x;
    if (i < NREL * NE) {
        int r = i / NE;
        int e = i - r * NE;
        int dst = edges[(size_t)r * 2 * NE + NE + e];
        atomicAdd(&g_cnt[r * NN + dst], 1);
    }
    if (i < NT * NN * DIN / 2) {
        float2 v = reinterpret_cast<const float2*>(x)[i];
        reinterpret_cast<__nv_bfloat162*>(g_xbf)[i] = __floats2bfloat162_rn(v.x, v.y);
    }
}

__global__ void k_scan() {
    int r = blockIdx.x;
    int t = threadIdx.x;
    __shared__ int s[1024];
    int carry = 0;
    for (int base = 0; base < NN; base += 1024) {
        int i = base + t;
        int v = (i < NN) ? g_cnt[r * NN + i] : 0;
        s[t] = v;
        __syncthreads();
        #pragma unroll
        for (int d = 1; d < 1024; d <<= 1) {
            int x = (t >= d) ? s[t - d] : 0;
            __syncthreads();
            s[t] += x;
            __syncthreads();
        }
        int excl = carry + s[t] - v;
        if (i < NN) {
            g_off[r * (NN + 1) + i] = excl;
            g_tmp[r * NN + i] = excl;
        }
        carry += s[1023];
        __syncthreads();
    }
    if (t == 0) g_off[r * (NN + 1) + NN] = carry;
}

__global__ void k_fill(const int* __restrict__ edges) {
    int i = blockIdx.x * blockDim.x + threadIdx.x;
    if (i >= NREL * NE) return;
    int r = i / NE;
    int e = i - r * NE;
    int src = edges[(size_t)r * 2 * NE + e];
    int dst = edges[(size_t)r * 2 * NE + NE + e];
    int pos = atomicAdd(&g_tmp[r * NN + dst], 1);
    g_csrc[(size_t)r * NE + pos] = src;
}

// ---------------------------------------------------------------------------
// Combine Wr / b across relations sharing a dst type (per-layer banks)
// ---------------------------------------------------------------------------
template <int K>
__global__ void k_combW(const float* __restrict__ Wr, float* __restrict__ wrc) {
    int idx = blockIdx.x * blockDim.x + threadIdx.x;
    if (idx >= NT * K * HH) return;
    int i = idx / (K * HH);
    int j = idx - i * (K * HH);
    float s = 0.f;
    #pragma unroll
    for (int r = 0; r < NREL; r++)
        if (c_dst[r] == i) s += Wr[(size_t)r * K * HH + j];
    wrc[(size_t)i * K * HH + j] = s;
}

__global__ void k_combB(const float* __restrict__ b, float* __restrict__ bc) {
    int idx = blockIdx.x * blockDim.x + threadIdx.x;
    if (idx >= NT * HH) return;
    int i = idx / HH;
    int j = idx - i * HH;
    float s = 0.f;
    #pragma unroll
    for (int r = 0; r < NREL; r++)
        if (c_dst[r] == i) s += b[r * HH + j];
    bc[i * HH + j] = s;
}

// ---------------------------------------------------------------------------
// bf16 gather aggregation, issue-optimized.
// Exact bf16->f32 via shift/mask (1 ALU op/elem), u32 byte addressing,
// 6 (D=128) / 12 (D=64) edges in flight per warp iteration.
// ---------------------------------------------------------------------------
__device__ __forceinline__ void accu4(float* a, uint4 u) {
    a[0] += __uint_as_float(u.x << 16);
    a[1] += __uint_as_float(u.x & 0xFFFF0000u);
    a[2] += __uint_as_float(u.y << 16);
    a[3] += __uint_as_float(u.y & 0xFFFF0000u);
    a[4] += __uint_as_float(u.z << 16);
    a[5] += __uint_as_float(u.z & 0xFFFF0000u);
    a[6] += __uint_as_float(u.w << 16);
    a[7] += __uint_as_float(u.w & 0xFFFF0000u);
}

template <int D>
__global__ void k_agg() {
    int r = blockIdx.y;
    int row = blockIdx.x * 8 + (threadIdx.x >> 5);
    int lane = threadIdx.x & 31;
    const char* __restrict__ bp =
        reinterpret_cast<const char*>(g_xbf + (size_t)c_src[r] * NN * D);
    float* __restrict__ msg = g_msgs + (size_t)r * NN * D;
    int o0 = g_off[r * (NN + 1) + row];
    int o1 = g_off[r * (NN + 1) + row + 1];
    const int* __restrict__ srcs = g_csrc + (size_t)r * NE;
    float inv = (o1 > o0) ? 1.f / (float)(o1 - o0) : 0.f;

    float a[8] = {0.f, 0.f, 0.f, 0.f, 0.f, 0.f, 0.f, 0.f};

    if (D == 128) {
        // half-warp covers 256B row; byte offset = s*256 + sub*16
        int half = lane >> 4;
        unsigned subo = (unsigned)(lane & 15) << 4;
        int e = o0;
        for (; e + 6 <= o1; e += 6) {
            unsigned s0 = (unsigned)srcs[e + half];
            unsigned s1 = (unsigned)srcs[e + 2 + half];
            unsigned s2 = (unsigned)srcs[e + 4 + half];
            uint4 u0 = *reinterpret_cast<const uint4*>(bp + ((s0 << 8) + subo));
            uint4 u1 = *reinterpret_cast<const uint4*>(bp + ((s1 << 8) + subo));
            uint4 u2 = *reinterpret_cast<const uint4*>(bp + ((s2 << 8) + subo));
            accu4(a, u0); accu4(a, u1); accu4(a, u2);
        }
        for (; e + 2 <= o1; e += 2) {
            unsigned s0 = (unsigned)srcs[e + half];
            uint4 u0 = *reinterpret_cast<const uint4*>(bp + ((s0 << 8) + subo));
            accu4(a, u0);
        }
        if (e < o1 && half == 0) {
            unsigned s0 = (unsigned)srcs[e];
            uint4 u0 = *reinterpret_cast<const uint4*>(bp + ((s0 << 8) + subo));
            accu4(a, u0);
        }
        #pragma unroll
        for (int k = 0; k < 8; k++)
            a[k] += __shfl_down_sync(0xffffffffu, a[k], 16);
        if (half == 0) {
            float* mp = msg + (size_t)row * 128 + (lane & 15) * 8;
            float4 v0 = make_float4(a[0] * inv, a[1] * inv, a[2] * inv, a[3] * inv);
            float4 v1 = make_float4(a[4] * inv, a[5] * inv, a[6] * inv, a[7] * inv);
            reinterpret_cast<float4*>(mp)[0] = v0;
            reinterpret_cast<float4*>(mp)[1] = v1;
        }
    } else {
        // quarter-warp covers 128B row; byte offset = s*128 + sub*16
        int q = lane >> 3;
        unsigned subo = (unsigned)(lane & 7) << 4;
        int e = o0;
        for (; e + 12 <= o1; e += 12) {
            unsigned s0 = (unsigned)srcs[e + q];
            unsigned s1 = (unsigned)srcs[e + 4 + q];
            unsigned s2 = (unsigned)srcs[e + 8 + q];
            uint4 u0 = *reinterpret_cast<const uint4*>(bp + ((s0 << 7) + subo));
            uint4 u1 = *reinterpret_cast<const uint4*>(bp + ((s1 << 7) + subo));
            uint4 u2 = *reinterpret_cast<const uint4*>(bp + ((s2 << 7) + subo));
            accu4(a, u0); accu4(a, u1); accu4(a, u2);
        }
        for (; e + 4 <= o1; e += 4) {
            unsigned s0 = (unsigned)srcs[e + q];
            uint4 u0 = *reinterpret_cast<const uint4*>(bp + ((s0 << 7) + subo));
            accu4(a, u0);
        }
        int rem = o1 - e;
        if (q < rem) {
            unsigned s0 = (unsigned)srcs[e + q];
            uint4 u0 = *reinterpret_cast<const uint4*>(bp + ((s0 << 7) + subo));
            accu4(a, u0);
        }
        #pragma unroll
        for (int k = 0; k < 8; k++) {
            a[k] += __shfl_down_sync(0xffffffffu, a[k], 16);
            a[k] += __shfl_down_sync(0xffffffffu, a[k], 8);
        }
        if (lane < 8) {
            float* mp = msg + (size_t)row * 64 + lane * 8;
            float4 v0 = make_float4(a[0] * inv, a[1] * inv, a[2] * inv, a[3] * inv);
            float4 v1 = make_float4(a[4] * inv, a[5] * inv, a[6] * inv, a[7] * inv);
            reinterpret_cast<float4*>(mp)[0] = v0;
            reinterpret_cast<float4*>(mp)[1] = v1;
        }
    }
}

// ---------------------------------------------------------------------------
// TF32 mma. A fragments re-rounded with cvt.rna in registers; B raw-truncated.
// ---------------------------------------------------------------------------
__device__ __forceinline__ uint32_t f2tf32(float f) {
    uint32_t u;
    asm("cvt.rna.tf32.f32 %0, %1;" : "=r"(u) : "f"(f));
    return u;
}

__device__ __forceinline__ void mma_tf32(float* d, const uint32_t* a, const uint32_t* b) {
    asm volatile(
        "mma.sync.aligned.m16n8k8.row.col.f32.tf32.tf32.f32 "
        "{%0,%1,%2,%3}, {%4,%5,%6,%7}, {%8,%9}, {%0,%1,%2,%3};"
        : "+f"(d[0]), "+f"(d[1]), "+f"(d[2]), "+f"(d[3])
        : "r"(a[0]), "r"(a[1]), "r"(a[2]), "r"(a[3]), "r"(b[0]), "r"(b[1]));
}

__device__ __forceinline__ void cp16(uint32_t dst, const void* src) {
    asm volatile("cp.async.cg.shared.global [%0], [%1], 16;" :: "r"(dst), "l"(src));
}

#define APAD 36
#define BPAD 136
#define ATILE (128 * APAD)
#define BTILE (32 * BPAD)
#define GSMEM ((2 * ATILE + 2 * BTILE) * 4)

// ---------------------------------------------------------------------------
// Segmented TF32 GEMM + fused leaky-ReLU + LayerNorm, cp.async double-buffered.
// grid (GBLK, NT); BM=128, BK=32, 8 warps, warp tile 16x128.
// ---------------------------------------------------------------------------
template <int SK, bool WRITEBF>
__global__ void __launch_bounds__(256) k_gemm_ln(const float* __restrict__ xin,
                                                const float* __restrict__ Wl,
                                                const float* __restrict__ wrc,
                                                const float* __restrict__ bc,
                                                const float* __restrict__ gam,
                                                const float* __restrict__ bet,
                                                float* __restrict__ out) {
    extern __shared__ uint32_t smem[];
    uint32_t* sA = smem;                  // 2 x ATILE
    uint32_t* sB = smem + 2 * ATILE;      // 2 x BTILE

    int tid = threadIdx.x;
    int lane = tid & 31;
    int w = tid >> 5;
    int type = blockIdx.y;
    int r0 = blockIdx.x * 128;

    uint32_t sAu = (uint32_t)__cvta_generic_to_shared(sA);
    uint32_t sBu = (uint32_t)__cvta_generic_to_shared(sB);

    constexpr int CH = SK / 32;
    int nchunk = c_nseg[type] * CH;

    auto issue = [&](int c, int buf) {
        int seg = c / CH;
        int off = (c - seg * CH) * 32;
        int rel = c_segrel[type][seg];
        const float* Ab = (seg == 0) ? xin + (size_t)type * NN * SK
                                     : g_msgs + (size_t)rel * NN * SK;
        const float* Bb = (seg == 0) ? wrc + (size_t)type * SK * HH
                                     : Wl + (size_t)rel * SK * HH;
        uint32_t dA = sAu + (uint32_t)buf * ATILE * 4;
        uint32_t dB = sBu + (uint32_t)buf * BTILE * 4;
        #pragma unroll
        for (int l = 0; l < 4; l++) {
            int f = tid + l * 256;
            int row = f >> 3;
            int c0 = (f & 7) * 4;
            int grow = r0 + row;
            if (grow > NN - 1) grow = NN - 1;   // clamp: junk rows masked at epilogue
            cp16(dA + (uint32_t)(row * APAD + c0) * 4,
                 Ab + (size_t)grow * SK + off + c0);
        }
        #pragma unroll
        for (int l = 0; l < 4; l++) {
            int f = tid + l * 256;
            int krow = f >> 5;
            int n0 = (f & 31) * 4;
            cp16(dB + (uint32_t)(krow * BPAD + n0) * 4,
                 Bb + (size_t)(off + krow) * HH + n0);
        }
        asm volatile("cp.async.commit_group;");
    };

    float acc[16][4];
    #pragma unroll
    for (int nt = 0; nt < 16; nt++)
        #pragma unroll
        for (int j = 0; j < 4; j++) acc[nt][j] = 0.f;

    issue(0, 0);
    for (int c = 0; c < nchunk; c++) {
        int buf = c & 1;
        if (c + 1 < nchunk) {
            issue(c + 1, buf ^ 1);
            asm volatile("cp.async.wait_group 1;");
        } else {
            asm volatile("cp.async.wait_group 0;");
        }
        __syncthreads();
        const uint32_t* cA = sA + buf * ATILE;
        const uint32_t* cB = sB + buf * BTILE;
        #pragma unroll
        for (int kt = 0; kt < 4; kt++) {
            int abase = (w * 16 + (lane >> 2)) * APAD + kt * 8 + (lane & 3);
            uint32_t af[4];
            af[0] = f2tf32(__uint_as_float(cA[abase]));
            af[1] = f2tf32(__uint_as_float(cA[abase + 8 * APAD]));
            af[2] = f2tf32(__uint_as_float(cA[abase + 4]));
            af[3] = f2tf32(__uint_as_float(cA[abase + 8 * APAD + 4]));
            int bb = (kt * 8 + (lane & 3)) * BPAD + (lane >> 2);
            #pragma unroll
            for (int nt = 0; nt < 16; nt++) {
                uint32_t bf[2];
                bf[0] = cB[bb + nt * 8];
                bf[1] = cB[bb + nt * 8 + 4 * BPAD];
                mma_tf32(acc[nt], af, bf);
            }
        }
        __syncthreads();
    }

    // ---- fused epilogue: bias, relation-mean, leaky ReLU, LayerNorm ----
    float inv = c_invcnt[type];
    #pragma unroll
    for (int h = 0; h < 2; h++) {
        int row = r0 + w * 16 + (lane >> 2) + h * 8;
        float v[16][2];
        float s = 0.f;
        #pragma unroll
        for (int nt = 0; nt < 16; nt++) {
            int col = nt * 8 + (lane & 3) * 2;
            float x0 = (acc[nt][2 * h] + bc[type * HH + col]) * inv;
            float x1 = (acc[nt][2 * h + 1] + bc[type * HH + col + 1]) * inv;
            x0 = (x0 >= 0.f) ? x0 : 0.01f * x0;
            x1 = (x1 >= 0.f) ? x1 : 0.01f * x1;
            v[nt][0] = x0; v[nt][1] = x1;
            s += x0 + x1;
        }
        s += __shfl_xor_sync(0xffffffffu, s, 1);
        s += __shfl_xor_sync(0xffffffffu, s, 2);
        float mu = s * (1.f / HH);
        float q = 0.f;
        #pragma unroll
        for (int nt = 0; nt < 16; nt++) {
            float d0 = v[nt][0] - mu, d1 = v[nt][1] - mu;
            v[nt][0] = d0; v[nt][1] = d1;
            q += d0 * d0 + d1 * d1;
        }
        q += __shfl_xor_sync(0xffffffffu, q, 1);
        q += __shfl_xor_sync(0xffffffffu, q, 2);
        float rs = rsqrtf(q * (1.f / HH) + 1e-5f);
        if (row < NN) {
            float* op = out + (size_t)type * NN * HH + (size_t)row * HH;
            __nv_bfloat16* obf = g_xbf + (size_t)type * NN * HH + (size_t)row * HH;
            #pragma unroll
            for (int nt = 0; nt < 16; nt++) {
                int col = nt * 8 + (lane & 3) * 2;
                float2 o;
                o.x = v[nt][0] * rs * gam[col] + bet[col];
                o.y = v[nt][1] * rs * gam[col + 1] + bet[col + 1];
                *reinterpret_cast<float2*>(op + col) = o;
                if (WRITEBF)
                    *reinterpret_cast<__nv_bfloat162*>(obf + col) =
                        __floats2bfloat162_rn(o.x, o.y);
            }
        }
    }
}

// ---------------------------------------------------------------------------
// Final: concat(9 types) @ Wfc + bfc, sigmoid
// ---------------------------------------------------------------------------
__device__ __forceinline__ float blockSum128(float v, float* sh) {
    #pragma unroll
    for (int o = 16; o > 0; o >>= 1) v += __shfl_xor_sync(0xffffffffu, v, o);
    int w = threadIdx.x >> 5;
    if ((threadIdx.x & 31) == 0) sh[w] = v;
    __syncthreads();
    float tot = sh[0] + sh[1] + sh[2] + sh[3];
    __syncthreads();
    return tot;
}

__global__ void k_final(const float* __restrict__ xs, const float* __restrict__ Wfc,
                        const float* __restrict__ bfc, float* __restrict__ out) {
    __shared__ float sh[4];
    int n = blockIdx.x;
    int t = threadIdx.x;
    float p = 0.f;
    #pragma unroll
    for (int i = 0; i < NT; i++)
        p += xs[((size_t)i * NN + n) * HH + t] * Wfc[i * HH + t];
    float tot = blockSum128(p, sh);
    if (t == 0) out[n] = 1.f / (1.f + expf(-(tot + bfc[0])));
}

// ---------------------------------------------------------------------------
// Host driver (single stream, serial)
// ---------------------------------------------------------------------------
extern "C" void kernel_launch(void* const* d_in, const int* in_sizes, int n_in,
                              void* d_out, int out_size) {
    const float* x    = (const float*)d_in[0];
    const int* edges  = (const int*)d_in[1];
    const float* Wl1  = (const float*)d_in[2];
    const float* Wr1  = (const float*)d_in[3];
    const float* b1   = (const float*)d_in[4];
    const float* Wl2  = (const float*)d_in[5];
    const float* Wr2  = (const float*)d_in[6];
    const float* b2   = (const float*)d_in[7];
    const float* Wl3  = (const float*)d_in[8];
    const float* Wr3  = (const float*)d_in[9];
    const float* b3   = (const float*)d_in[10];
    const float* g1   = (const float*)d_in[11];
    const float* be1  = (const float*)d_in[12];
    const float* g2   = (const float*)d_in[13];
    const float* be2  = (const float*)d_in[14];
    const float* g3   = (const float*)d_in[15];
    const float* be3  = (const float*)d_in[16];
    const float* Wfc  = (const float*)d_in[17];
    const float* bfc  = (const float*)d_in[18];
    float* out = (float*)d_out;

    float *p_xs0, *p_xs1, *p_wrc, *p_bc;
    int* p_cnt;
    cudaGetSymbolAddress((void**)&p_xs0, g_xs0);
    cudaGetSymbolAddress((void**)&p_xs1, g_xs1);
    cudaGetSymbolAddress((void**)&p_wrc, g_wrc);
    cudaGetSymbolAddress((void**)&p_bc, g_bc);
    cudaGetSymbolAddress((void**)&p_cnt, g_cnt);

    cudaFuncSetAttribute(k_gemm_ln<DIN, true>,
                         cudaFuncAttributeMaxDynamicSharedMemorySize, GSMEM);
    cudaFuncSetAttribute(k_gemm_ln<HH, true>,
                         cudaFuncAttributeMaxDynamicSharedMemorySize, GSMEM);
    cudaFuncSetAttribute(k_gemm_ln<HH, false>,
                         cudaFuncAttributeMaxDynamicSharedMemorySize, GSMEM);

    size_t wstride = (size_t)NT * HH * HH;

    // CSR build chain (g_cnt zeroed via async memset — graph-capturable)
    cudaMemsetAsync(p_cnt, 0, (size_t)NREL * NN * sizeof(int));
    k_hist_cvt<<<(NT * NN * DIN / 2 + 255) / 256, 256>>>(edges, x);
    k_scan<<<NREL, 1024>>>();
    k_fill<<<(NREL * NE + 255) / 256, 256>>>(edges);

    // layer-1 aggregation (ncu-visible launch)
    k_agg<DIN><<<dim3(NN / 8, NREL), 256>>>();

    // weight prep (all layers)
    k_combW<DIN><<<(NT * DIN * HH + 255) / 256, 256>>>(Wr1, p_wrc);
    k_combW<HH><<<(NT * HH * HH + 255) / 256, 256>>>(Wr2, p_wrc + wstride);
    k_combW<HH><<<(NT * HH * HH + 255) / 256, 256>>>(Wr3, p_wrc + 2 * wstride);
    k_combB<<<(NT * HH + 255) / 256, 256>>>(b1, p_bc);
    k_combB<<<(NT * HH + 255) / 256, 256>>>(b2, p_bc + NT * HH);
    k_combB<<<(NT * HH + 255) / 256, 256>>>(b3, p_bc + 2 * NT * HH);

    dim3 gg((NN + 127) / 128, NT);
    dim3 ga(NN / 8, NREL);

    // layer 1
    k_gemm_ln<DIN, true><<<gg, 256, GSMEM>>>(x, Wl1, p_wrc, p_bc, g1, be1, p_xs0);
    // layer 2
    k_agg<HH><<<ga, 256>>>();
    k_gemm_ln<HH, true><<<gg, 256, GSMEM>>>(p_xs0, Wl2, p_wrc + wstride,
                                            p_bc + NT * HH, g2, be2, p_xs1);
    // layer 3
    k_agg<HH><<<ga, 256>>>();
    k_gemm_ln<HH, false><<<gg, 256, GSMEM>>>(p_xs1, Wl3, p_wrc + 2 * wstride,
                                             p_bc + 2 * NT * HH, g3, be3, p_xs0);

    k_final<<<NN, HH>>>(p_xs0, Wfc, bfc, out);
}